// round 1
// baseline (speedup 1.0000x reference)
#include <cuda_runtime.h>
#include <math.h>

static constexpr int B_ = 16, C_ = 16, P_ = 512, D_ = 256;

// Scratch (device globals; allocation in kernel_launch is forbidden)
__device__ float g_context[(size_t)B_ * C_ * P_ * D_];   // 134 MB
__device__ float g_q[(size_t)B_ * C_ * P_ * D_];
__device__ float g_k[(size_t)B_ * C_ * P_ * D_];
__device__ float g_v[(size_t)B_ * C_ * P_ * D_];
__device__ float g_scores[(size_t)B_ * C_ * P_ * P_];    // 268 MB

// ---------------------------------------------------------------------------
// 1) context[b,c,p,d] = sum_c'(aw[c',p,d]*q[b,c',p,d]) - aw[c,p,d]*q[b,c,p,d]
// ---------------------------------------------------------------------------
__global__ void context_kernel(const float* __restrict__ query,
                               const float* __restrict__ aw)
{
    int idx = blockIdx.x * blockDim.x + threadIdx.x;   // over B*P*D
    if (idx >= B_ * P_ * D_) return;
    int b  = idx / (P_ * D_);
    int pd = idx - b * (P_ * D_);

    const float* qb  = query + (size_t)b * C_ * P_ * D_ + pd;
    const float* awp = aw + pd;

    float acw[C_];
    float s = 0.f;
    #pragma unroll
    for (int c = 0; c < C_; c++) {
        float v = awp[(size_t)c * P_ * D_] * qb[(size_t)c * P_ * D_];
        acw[c] = v;
        s += v;
    }
    float* ctx = g_context + (size_t)b * C_ * P_ * D_ + pd;
    #pragma unroll
    for (int c = 0; c < C_; c++)
        ctx[(size_t)c * P_ * D_] = s - acw[c];
}

// ---------------------------------------------------------------------------
// 2) Unified batched fp32 GEMM: C[z] = A[z] (M=128*gridDim.x x K) * B[z%bMod]
//    BM=BN=128, BK=16, 256 threads, 8x8 per-thread microtile.
//    TRANSB: B accessed as B[n*ldb + k] (for q @ k^T).
//    RELU:   epilogue v = max(v + bias[n], 0) * scale ; else v *= scale.
// ---------------------------------------------------------------------------
template<int K, bool TRANSB, bool RELU>
__global__ __launch_bounds__(256, 2)
void gemm_kernel(const float* __restrict__ A0, const float* __restrict__ B0,
                 const float* __restrict__ bias0, float* __restrict__ C0,
                 int lda, int ldb, int ldc,
                 size_t aBatch, size_t bBatch, size_t cBatch,
                 int bMod, float scale)
{
    constexpr int BM = 128, BN = 128, BK = 16;
    __shared__ float As[BK][BM];
    __shared__ float Bs[BK][BN];

    const int tid = threadIdx.x;
    const int z   = blockIdx.z;
    const int n0  = blockIdx.y * BN;

    const float* Ap = A0 + (size_t)z * aBatch + (size_t)blockIdx.x * BM * lda;
    const float* Bp = B0 + (size_t)(z % bMod) * bBatch;

    float acc[8][8];
    #pragma unroll
    for (int i = 0; i < 8; i++)
        #pragma unroll
        for (int j = 0; j < 8; j++) acc[i][j] = 0.f;

    const int tx = tid & 15, ty = tid >> 4;

    for (int k0 = 0; k0 < K; k0 += BK) {
        // --- load A tile (BM x BK), store transposed to As[kk][m] ---
        {
            int r  = tid >> 2;          // 0..63
            int cc = (tid & 3) * 4;     // 0,4,8,12
            #pragma unroll
            for (int i = 0; i < 2; i++) {
                int rr = r + i * 64;
                float4 v = *(const float4*)(Ap + (size_t)rr * lda + k0 + cc);
                As[cc + 0][rr] = v.x; As[cc + 1][rr] = v.y;
                As[cc + 2][rr] = v.z; As[cc + 3][rr] = v.w;
            }
        }
        // --- load B tile ---
        if (TRANSB) {
            int r  = tid >> 2;          // n index 0..63
            int cc = (tid & 3) * 4;     // kk
            #pragma unroll
            for (int i = 0; i < 2; i++) {
                int rr = r + i * 64;
                float4 v = *(const float4*)(Bp + (size_t)(n0 + rr) * ldb + k0 + cc);
                Bs[cc + 0][rr] = v.x; Bs[cc + 1][rr] = v.y;
                Bs[cc + 2][rr] = v.z; Bs[cc + 3][rr] = v.w;
            }
        } else {
            int r  = tid >> 5;          // kk 0..7
            int cc = (tid & 31) * 4;    // n
            #pragma unroll
            for (int i = 0; i < 2; i++) {
                *(float4*)&Bs[r + i * 8][cc] =
                    *(const float4*)(Bp + (size_t)(k0 + r + i * 8) * ldb + n0 + cc);
            }
        }
        __syncthreads();

        #pragma unroll
        for (int kk = 0; kk < BK; kk++) {
            float a[8], bv[8];
            *(float4*)&a[0]  = *(const float4*)&As[kk][ty * 8];
            *(float4*)&a[4]  = *(const float4*)&As[kk][ty * 8 + 4];
            *(float4*)&bv[0] = *(const float4*)&Bs[kk][tx * 8];
            *(float4*)&bv[4] = *(const float4*)&Bs[kk][tx * 8 + 4];
            #pragma unroll
            for (int i = 0; i < 8; i++)
                #pragma unroll
                for (int j = 0; j < 8; j++)
                    acc[i][j] = fmaf(a[i], bv[j], acc[i][j]);
        }
        __syncthreads();
    }

    // --- epilogue ---
    float bb[8];
    if (RELU) {
        const float* biasp = bias0 + (size_t)(z % bMod) * D_ + n0 + tx * 8;
        #pragma unroll
        for (int j = 0; j < 8; j++) bb[j] = biasp[j];
    }
    float* Cp = C0 + (size_t)z * cBatch
                   + (size_t)(blockIdx.x * BM + ty * 8) * ldc + n0 + tx * 8;
    #pragma unroll
    for (int i = 0; i < 8; i++) {
        float tmp[8];
        #pragma unroll
        for (int j = 0; j < 8; j++) {
            float v = acc[i][j];
            if (RELU) v = fmaxf(v + bb[j], 0.f);
            tmp[j] = v * scale;
        }
        float* orow = Cp + (size_t)i * ldc;
        *(float4*)&orow[0] = *(float4*)&tmp[0];
        *(float4*)&orow[4] = *(float4*)&tmp[4];
    }
}

// ---------------------------------------------------------------------------
// 3) Softmax over rows of g_scores (row length P_=512). One warp per row.
// ---------------------------------------------------------------------------
__global__ void softmax_kernel()
{
    int gw   = (blockIdx.x * blockDim.x + threadIdx.x) >> 5;
    int lane = threadIdx.x & 31;
    if (gw >= B_ * C_ * P_) return;

    float4* row = reinterpret_cast<float4*>(g_scores) + (size_t)gw * (P_ / 4);

    float4 v[4];
    float m = -1e30f;
    #pragma unroll
    for (int i = 0; i < 4; i++) {
        v[i] = row[lane + 32 * i];
        m = fmaxf(m, fmaxf(fmaxf(v[i].x, v[i].y), fmaxf(v[i].z, v[i].w)));
    }
    #pragma unroll
    for (int o = 16; o > 0; o >>= 1)
        m = fmaxf(m, __shfl_xor_sync(0xffffffffu, m, o));

    float s = 0.f;
    #pragma unroll
    for (int i = 0; i < 4; i++) {
        v[i].x = __expf(v[i].x - m);
        v[i].y = __expf(v[i].y - m);
        v[i].z = __expf(v[i].z - m);
        v[i].w = __expf(v[i].w - m);
        s += v[i].x + v[i].y + v[i].z + v[i].w;
    }
    #pragma unroll
    for (int o = 16; o > 0; o >>= 1)
        s += __shfl_xor_sync(0xffffffffu, s, o);

    float inv = 1.0f / s;
    #pragma unroll
    for (int i = 0; i < 4; i++) {
        v[i].x *= inv; v[i].y *= inv; v[i].z *= inv; v[i].w *= inv;
        row[lane + 32 * i] = v[i];
    }
}

// ---------------------------------------------------------------------------
// launch
// ---------------------------------------------------------------------------
extern "C" void kernel_launch(void* const* d_in, const int* in_sizes, int n_in,
                              void* d_out, int out_size)
{
    const float* query = (const float*)d_in[0];
    const float* aw    = (const float*)d_in[1];
    const float* wq    = (const float*)d_in[2];
    const float* wk    = (const float*)d_in[3];
    const float* wv    = (const float*)d_in[4];
    const float* bq    = (const float*)d_in[5];
    const float* bk    = (const float*)d_in[6];
    const float* bv    = (const float*)d_in[7];
    float* out = (float*)d_out;

    float *gctx, *gq, *gk, *gv, *gsc;
    cudaGetSymbolAddress((void**)&gctx, g_context);
    cudaGetSymbolAddress((void**)&gq, g_q);
    cudaGetSymbolAddress((void**)&gk, g_k);
    cudaGetSymbolAddress((void**)&gv, g_v);
    cudaGetSymbolAddress((void**)&gsc, g_scores);

    const float qscale = 1.0f / 16.0f;   // D^-0.5, D=256
    const size_t PD = (size_t)P_ * D_;
    const size_t PP = (size_t)P_ * P_;
    const size_t DD = (size_t)D_ * D_;

    // 1) context
    context_kernel<<<(B_ * P_ * D_) / 256, 256>>>(query, aw);

    // 2) projections: per (b,c) GEMM 512 x 256 x 256, bias+relu (+scale for q)
    dim3 gp(4, 2, B_ * C_);
    gemm_kernel<D_, false, true><<<gp, 256>>>(query, wq, bq, gq,
        D_, D_, D_, PD, DD, PD, C_, qscale);
    gemm_kernel<D_, false, true><<<gp, 256>>>(gctx, wk, bk, gk,
        D_, D_, D_, PD, DD, PD, C_, 1.0f);
    gemm_kernel<D_, false, true><<<gp, 256>>>(gctx, wv, bv, gv,
        D_, D_, D_, PD, DD, PD, C_, 1.0f);

    // 3) scores = q @ k^T  per (b,c): 512 x 512 x 256
    dim3 gs(4, 4, B_ * C_);
    gemm_kernel<D_, true, false><<<gs, 256>>>(gq, gk, nullptr, gsc,
        D_, D_, P_, PD, PD, PP, B_ * C_, 1.0f);

    // 4) softmax in-place on scores
    softmax_kernel<<<(B_ * C_ * P_) / 8, 256>>>();

    // 5) out = attn @ v  per (b,c): 512 x 256 x 512
    dim3 go(4, 2, B_ * C_);
    gemm_kernel<P_, false, false><<<go, 256>>>(gsc, gv, nullptr, out,
        P_, D_, D_, PP, PD, PD, B_ * C_, 1.0f);
}

// round 2
// speedup vs baseline: 2.8460x; 2.8460x over previous
#include <cuda_runtime.h>
#include <math.h>
#include <stdint.h>

static constexpr int B_ = 16, C_ = 16, P_ = 512, D_ = 256;

// Scratch (device globals; allocation in kernel_launch is forbidden)
__device__ float g_context[(size_t)B_ * C_ * P_ * D_];
__device__ float g_q[(size_t)B_ * C_ * P_ * D_];
__device__ float g_k[(size_t)B_ * C_ * P_ * D_];
__device__ float g_v[(size_t)B_ * C_ * P_ * D_];
__device__ float g_scores[(size_t)B_ * C_ * P_ * P_];

// ---------------------------------------------------------------------------
// helpers
// ---------------------------------------------------------------------------
__device__ __forceinline__ void cpasync16(void* smem, const void* gmem) {
    unsigned s = (unsigned)__cvta_generic_to_shared(smem);
    asm volatile("cp.async.cg.shared.global [%0], [%1], 16;\n" :: "r"(s), "l"(gmem));
}
__device__ __forceinline__ uint32_t f2tf32(float f) {
    uint32_t u; asm("cvt.rna.tf32.f32 %0, %1;" : "=r"(u) : "f"(f)); return u;
}
__device__ __forceinline__ void mma_tf32(float* c, const uint32_t* a, const uint32_t* b) {
    asm volatile(
        "mma.sync.aligned.m16n8k8.row.col.f32.tf32.tf32.f32 "
        "{%0,%1,%2,%3}, {%4,%5,%6,%7}, {%8,%9}, {%0,%1,%2,%3};"
        : "+f"(c[0]), "+f"(c[1]), "+f"(c[2]), "+f"(c[3])
        : "r"(a[0]), "r"(a[1]), "r"(a[2]), "r"(a[3]), "r"(b[0]), "r"(b[1]));
}

// ---------------------------------------------------------------------------
// 1) context = rowsum-over-C(aw*q) - aw*q
// ---------------------------------------------------------------------------
__global__ void context_kernel(const float* __restrict__ query,
                               const float* __restrict__ aw)
{
    int idx = blockIdx.x * blockDim.x + threadIdx.x;
    if (idx >= B_ * P_ * D_) return;
    int b  = idx / (P_ * D_);
    int pd = idx - b * (P_ * D_);

    const float* qb  = query + (size_t)b * C_ * P_ * D_ + pd;
    const float* awp = aw + pd;

    float acw[C_];
    float s = 0.f;
    #pragma unroll
    for (int c = 0; c < C_; c++) {
        float v = awp[(size_t)c * P_ * D_] * qb[(size_t)c * P_ * D_];
        acw[c] = v;
        s += v;
    }
    float* ctx = g_context + (size_t)b * C_ * P_ * D_ + pd;
    #pragma unroll
    for (int c = 0; c < C_; c++)
        ctx[(size_t)c * P_ * D_] = s - acw[c];
}

// ---------------------------------------------------------------------------
// 2) Batched TF32 tensor-core GEMM.
//    C[z](M x N) = A[z](M x K, row-major) * B[z % bMod]
//    TRANSB=1: B is (N x K) row-major (q @ k^T).  TRANSB=0: B is (K x N) row-major.
//    BM=BN=128, BK=16; 256 threads = 8 warps, each warp 64x32 via 4x4 m16n8k8.
// ---------------------------------------------------------------------------
template<int K, bool TRANSB, bool RELU>
__global__ __launch_bounds__(256, 2)
void mma_gemm(const float* __restrict__ A0, const float* __restrict__ B0,
              const float* __restrict__ bias0, float* __restrict__ C0,
              int lda, int ldb, int ldc,
              size_t aB, size_t bB, size_t cB, int bMod, float scale)
{
    constexpr int BM = 128, BN = 128, BK = 16;
    constexpr int ASTR  = 20;    // As[m][k] row stride (floats) — conflict-free frag loads
    constexpr int BTSTR = 20;    // Bs[n][k] (TRANSB)
    constexpr int BNSTR = 136;   // Bs[k][n] (no trans)
    constexpr int BS_ELEMS = 2560;  // max(128*20, 16*136)

    __shared__ float As[2][BM * ASTR];
    __shared__ float Bs[2][BS_ELEMS];

    const int tid  = threadIdx.x;
    const int lane = tid & 31;
    const int warp = tid >> 5;
    const int wm = warp >> 2;          // 0..1
    const int wn = warp & 3;           // 0..3
    const int z  = blockIdx.z;
    const int m_blk = blockIdx.x * BM;
    const int n_blk = blockIdx.y * BN;

    const float* Ap = A0 + (size_t)z * aB + (size_t)m_blk * lda;
    const float* Bp = B0 + (size_t)(z % bMod) * bB;

    float acc[4][4][4];
    #pragma unroll
    for (int i = 0; i < 4; i++)
        #pragma unroll
        for (int j = 0; j < 4; j++)
            #pragma unroll
            for (int r = 0; r < 4; r++) acc[i][j][r] = 0.f;

    const int arow = tid >> 2;         // 0..63
    const int aq   = (tid & 3) * 4;    // 0,4,8,12

    auto load_tile = [&](int k0, int buf) {
        #pragma unroll
        for (int i = 0; i < 2; i++) {
            int r = arow + i * 64;
            cpasync16(&As[buf][r * ASTR + aq], Ap + (size_t)r * lda + k0 + aq);
        }
        if (TRANSB) {
            #pragma unroll
            for (int i = 0; i < 2; i++) {
                int r = arow + i * 64;
                cpasync16(&Bs[buf][r * BTSTR + aq],
                          Bp + (size_t)(n_blk + r) * ldb + k0 + aq);
            }
        } else {
            int kr = tid >> 5;            // 0..7
            int nq = (tid & 31) * 4;      // 0..124
            #pragma unroll
            for (int i = 0; i < 2; i++) {
                int kk = kr + i * 8;
                cpasync16(&Bs[buf][kk * BNSTR + nq],
                          Bp + (size_t)(k0 + kk) * ldb + n_blk + nq);
            }
        }
        asm volatile("cp.async.commit_group;\n");
    };

    int buf = 0;
    load_tile(0, 0);
    constexpr int NT = K / BK;

    #pragma unroll 1
    for (int t = 0; t < NT; t++) {
        if (t + 1 < NT) {
            load_tile((t + 1) * BK, buf ^ 1);
            asm volatile("cp.async.wait_group 1;\n");
        } else {
            asm volatile("cp.async.wait_group 0;\n");
        }
        __syncthreads();

        #pragma unroll
        for (int ks = 0; ks < BK; ks += 8) {
            uint32_t afr[4][4];
            #pragma unroll
            for (int i = 0; i < 4; i++) {
                int r = wm * 64 + i * 16 + (lane >> 2);
                afr[i][0] = f2tf32(As[buf][r * ASTR + ks + (lane & 3)]);
                afr[i][1] = f2tf32(As[buf][(r + 8) * ASTR + ks + (lane & 3)]);
                afr[i][2] = f2tf32(As[buf][r * ASTR + ks + 4 + (lane & 3)]);
                afr[i][3] = f2tf32(As[buf][(r + 8) * ASTR + ks + 4 + (lane & 3)]);
            }
            uint32_t bfr[4][2];
            #pragma unroll
            for (int j = 0; j < 4; j++) {
                int n0 = wn * 32 + j * 8;
                float g0, g1;
                if (TRANSB) {
                    g0 = Bs[buf][(n0 + (lane >> 2)) * BTSTR + ks + (lane & 3)];
                    g1 = Bs[buf][(n0 + (lane >> 2)) * BTSTR + ks + 4 + (lane & 3)];
                } else {
                    g0 = Bs[buf][(ks + (lane & 3)) * BNSTR + n0 + (lane >> 2)];
                    g1 = Bs[buf][(ks + 4 + (lane & 3)) * BNSTR + n0 + (lane >> 2)];
                }
                bfr[j][0] = f2tf32(g0);
                bfr[j][1] = f2tf32(g1);
            }
            #pragma unroll
            for (int i = 0; i < 4; i++)
                #pragma unroll
                for (int j = 0; j < 4; j++)
                    mma_tf32(acc[i][j], afr[i], bfr[j]);
        }
        __syncthreads();
        buf ^= 1;
    }

    // epilogue
    float* Cbase = C0 + (size_t)z * cB;
    #pragma unroll
    for (int j = 0; j < 4; j++) {
        int cidx = n_blk + wn * 32 + j * 8 + 2 * (lane & 3);
        float b0 = 0.f, b1 = 0.f;
        if (RELU) {
            const float* bp = bias0 + (size_t)(z % bMod) * D_ + cidx;
            b0 = bp[0]; b1 = bp[1];
        }
        #pragma unroll
        for (int i = 0; i < 4; i++) {
            int r0 = m_blk + wm * 64 + i * 16 + (lane >> 2);
            float v0 = acc[i][j][0], v1 = acc[i][j][1];
            float v2 = acc[i][j][2], v3 = acc[i][j][3];
            if (RELU) {
                v0 = fmaxf(v0 + b0, 0.f); v1 = fmaxf(v1 + b1, 0.f);
                v2 = fmaxf(v2 + b0, 0.f); v3 = fmaxf(v3 + b1, 0.f);
            }
            v0 *= scale; v1 *= scale; v2 *= scale; v3 *= scale;
            *(float2*)(Cbase + (size_t)r0 * ldc + cidx)       = make_float2(v0, v1);
            *(float2*)(Cbase + (size_t)(r0 + 8) * ldc + cidx) = make_float2(v2, v3);
        }
    }
}

// ---------------------------------------------------------------------------
// 3) Softmax over rows of g_scores (row length 512). One warp per row.
// ---------------------------------------------------------------------------
__global__ void softmax_kernel()
{
    int gw   = (blockIdx.x * blockDim.x + threadIdx.x) >> 5;
    int lane = threadIdx.x & 31;
    if (gw >= B_ * C_ * P_) return;

    float4* row = reinterpret_cast<float4*>(g_scores) + (size_t)gw * (P_ / 4);

    float4 v[4];
    float m = -1e30f;
    #pragma unroll
    for (int i = 0; i < 4; i++) {
        v[i] = row[lane + 32 * i];
        m = fmaxf(m, fmaxf(fmaxf(v[i].x, v[i].y), fmaxf(v[i].z, v[i].w)));
    }
    #pragma unroll
    for (int o = 16; o > 0; o >>= 1)
        m = fmaxf(m, __shfl_xor_sync(0xffffffffu, m, o));

    float s = 0.f;
    #pragma unroll
    for (int i = 0; i < 4; i++) {
        v[i].x = __expf(v[i].x - m);
        v[i].y = __expf(v[i].y - m);
        v[i].z = __expf(v[i].z - m);
        v[i].w = __expf(v[i].w - m);
        s += v[i].x + v[i].y + v[i].z + v[i].w;
    }
    #pragma unroll
    for (int o = 16; o > 0; o >>= 1)
        s += __shfl_xor_sync(0xffffffffu, s, o);

    float inv = 1.0f / s;
    #pragma unroll
    for (int i = 0; i < 4; i++) {
        v[i].x *= inv; v[i].y *= inv; v[i].z *= inv; v[i].w *= inv;
        row[lane + 32 * i] = v[i];
    }
}

// ---------------------------------------------------------------------------
// launch
// ---------------------------------------------------------------------------
extern "C" void kernel_launch(void* const* d_in, const int* in_sizes, int n_in,
                              void* d_out, int out_size)
{
    const float* query = (const float*)d_in[0];
    const float* aw    = (const float*)d_in[1];
    const float* wq    = (const float*)d_in[2];
    const float* wk    = (const float*)d_in[3];
    const float* wv    = (const float*)d_in[4];
    const float* bq    = (const float*)d_in[5];
    const float* bk    = (const float*)d_in[6];
    const float* bv    = (const float*)d_in[7];
    float* out = (float*)d_out;

    float *gctx, *gq, *gk, *gv, *gsc;
    cudaGetSymbolAddress((void**)&gctx, g_context);
    cudaGetSymbolAddress((void**)&gq, g_q);
    cudaGetSymbolAddress((void**)&gk, g_k);
    cudaGetSymbolAddress((void**)&gv, g_v);
    cudaGetSymbolAddress((void**)&gsc, g_scores);

    const float qscale = 1.0f / 16.0f;   // D^-0.5
    const size_t PD = (size_t)P_ * D_;
    const size_t PP = (size_t)P_ * P_;
    const size_t DD = (size_t)D_ * D_;

    // 1) context
    context_kernel<<<(B_ * P_ * D_) / 256, 256>>>(query, aw);

    // 2) projections: per (b,c) GEMM 512 x 256 x 256, bias+relu (+scale for q)
    dim3 gp(4, 2, B_ * C_);
    mma_gemm<D_, false, true><<<gp, 256>>>(query, wq, bq, gq,
        D_, D_, D_, PD, DD, PD, C_, qscale);
    mma_gemm<D_, false, true><<<gp, 256>>>(gctx, wk, bk, gk,
        D_, D_, D_, PD, DD, PD, C_, 1.0f);
    mma_gemm<D_, false, true><<<gp, 256>>>(gctx, wv, bv, gv,
        D_, D_, D_, PD, DD, PD, C_, 1.0f);

    // 3) scores = q @ k^T  per (b,c): 512 x 512 x 256
    dim3 gs(4, 4, B_ * C_);
    mma_gemm<D_, true, false><<<gs, 256>>>(gq, gk, nullptr, gsc,
        D_, D_, P_, PD, PD, PP, B_ * C_, 1.0f);

    // 4) softmax in-place on scores
    softmax_kernel<<<(B_ * C_ * P_) / 8, 256>>>();

    // 5) out = attn @ v  per (b,c): 512 x 256 x 512
    dim3 go(4, 2, B_ * C_);
    mma_gemm<P_, false, false><<<go, 256>>>(gsc, gv, nullptr, out,
        P_, D_, D_, PP, PD, PD, B_ * C_, 1.0f);
}